// round 5
// baseline (speedup 1.0000x reference)
#include <cuda_runtime.h>
#include <math.h>

#define S_LEN  1024
#define BATCH  4
#define DMODEL 1024
#define NHEAD  16
#define DHEAD  64

// ---------------- device scratch ----------------
// head-major qkv: idx = (((which*BATCH + b)*NHEAD + h)*S_LEN + s)*DHEAD + d
__device__ float g_qkv[3 * BATCH * NHEAD * S_LEN * DHEAD];
__device__ float g_concat[S_LEN * BATCH * DMODEL];   // [row = s*B+b][h*64+d]

// ---------------- helpers ----------------
__device__ __forceinline__ unsigned f2tf(float f) {
    unsigned u;
    asm("cvt.rna.tf32.f32 %0, %1;" : "=r"(u) : "f"(f));
    return u;
}

#define MMA_TF32(d, a, b)                                                        \
    asm volatile(                                                                \
        "mma.sync.aligned.m16n8k8.row.col.f32.tf32.tf32.f32 "                    \
        "{%0,%1,%2,%3}, {%4,%5,%6,%7}, {%8,%9}, {%0,%1,%2,%3};"                  \
        : "+f"((d)[0]), "+f"((d)[1]), "+f"((d)[2]), "+f"((d)[3])                 \
        : "r"((a)[0]), "r"((a)[1]), "r"((a)[2]), "r"((a)[3]),                    \
          "r"((b)[0]), "r"((b)[1]))

// ---------------- TF32 GEMM: 128x128x32 tile, 8 warps, double-buffered smem ----------------
// Fragment-order layout per stage (8192 words):
//   A frag group (kb,mg): (kb*8+mg)*128 + ((lane^kb)<<2)  -> one uint4 per lane
//   B frag group (kb,ng): 4096 + (kb*16+ng)*64 + ((lane^ng)<<1) -> one uint2 per lane
#define GEMM_SMEM_BYTES (2 * 8192 * 4)

template<int QKV>
__device__ __forceinline__ void gemm_body(
    const float* __restrict__ A, const float* __restrict__ Bthr, int ldbf,
    const float* __restrict__ biasP, float* __restrict__ C,
    int lda, int ldc, int m0, int n0)
{
    extern __shared__ unsigned gsm[];

    const int tid  = threadIdx.x;
    const int lane = tid & 31;
    const int wid  = tid >> 5;
    const int gid  = lane >> 2;
    const int tig  = lane & 3;

    float acc[4][4][4];
#pragma unroll
    for (int mt = 0; mt < 4; ++mt)
#pragma unroll
        for (int nt = 0; nt < 4; ++nt)
#pragma unroll
            for (int r = 0; r < 4; ++r) acc[mt][nt][r] = 0.f;

    // global A mapping
    const int arow  = tid >> 3;              // 0..31
    const int acol  = (tid & 7) << 2;        // k offset 0..28
    const int a_kb  = acol >> 3;
    const int a_chi = (acol >> 2) & 1;
    const int a_gid = arow & 7;
    const int a_hi  = (arow >> 3) & 1;
    const int a_mgb = arow >> 4;
    // global B mapping
    const int b_brow = tid >> 5;             // 0..7 (k row within 8)
    const int bcol   = (tid & 31) << 2;      // n offset 0..124
    const int b_tig  = b_brow & 3;
    const int b_hi   = (b_brow >> 2) & 1;
    const int b_ng   = bcol >> 3;
    const int b_gidb = bcol & 7;

    const float* Ap = A + (size_t)(m0 + arow) * lda + acol;

    float4 ag[4], bg[4];
#pragma unroll
    for (int r = 0; r < 4; ++r) ag[r] = *(const float4*)(Ap + (size_t)(32 * r) * lda);
#pragma unroll
    for (int r = 0; r < 4; ++r) bg[r] = *(const float4*)(Bthr + (size_t)(8 * r) * ldbf);

    const int mgw = (wid >> 2) * 4;
    const int ngw = (wid & 3) * 4;

    for (int t = 0; t < DMODEL / 32; ++t) {
        unsigned* As = gsm + (t & 1) * 8192;
        unsigned* Bs = As + 4096;

        // ---- stage tile t ----
#pragma unroll
        for (int r = 0; r < 4; ++r) {
            unsigned* dst = &As[(a_kb * 8 + a_mgb + 2 * r) * 128 + a_hi + 2 * a_chi];
            dst[(a_gid * 4 + (0 ^ a_kb)) * 4] = f2tf(ag[r].x);
            dst[(a_gid * 4 + (1 ^ a_kb)) * 4] = f2tf(ag[r].y);
            dst[(a_gid * 4 + (2 ^ a_kb)) * 4] = f2tf(ag[r].z);
            dst[(a_gid * 4 + (3 ^ a_kb)) * 4] = f2tf(ag[r].w);
        }
#pragma unroll
        for (int r = 0; r < 4; ++r) {
            unsigned* dst = &Bs[(r * 16 + b_ng) * 64 + b_hi];
            dst[((((b_gidb + 0) * 4 + b_tig) ^ b_ng)) * 2] = f2tf(bg[r].x);
            dst[((((b_gidb + 1) * 4 + b_tig) ^ b_ng)) * 2] = f2tf(bg[r].y);
            dst[((((b_gidb + 2) * 4 + b_tig) ^ b_ng)) * 2] = f2tf(bg[r].z);
            dst[((((b_gidb + 3) * 4 + b_tig) ^ b_ng)) * 2] = f2tf(bg[r].w);
        }
        __syncthreads();

        // ---- prefetch tile t+1 (latency hidden under MMAs below) ----
        if (t + 1 < DMODEL / 32) {
            int k0 = (t + 1) * 32;
#pragma unroll
            for (int r = 0; r < 4; ++r)
                ag[r] = *(const float4*)(Ap + (size_t)(32 * r) * lda + k0);
#pragma unroll
            for (int r = 0; r < 4; ++r)
                bg[r] = *(const float4*)(Bthr + (size_t)(k0 + 8 * r) * ldbf);
        }

        // ---- compute tile t ----
#pragma unroll
        for (int kb = 0; kb < 4; ++kb) {
            unsigned af[4][4], bf[4][2];
            const int la = (lane ^ kb) << 2;
#pragma unroll
            for (int mt = 0; mt < 4; ++mt) {
                uint4 tt = *(const uint4*)&As[(kb * 8 + mgw + mt) * 128 + la];
                af[mt][0] = tt.x; af[mt][1] = tt.y; af[mt][2] = tt.z; af[mt][3] = tt.w;
            }
#pragma unroll
            for (int nt = 0; nt < 4; ++nt) {
                int ng = ngw + nt;
                uint2 tt = *(const uint2*)&Bs[(kb * 16 + ng) * 64 + ((lane ^ ng) << 1)];
                bf[nt][0] = tt.x; bf[nt][1] = tt.y;
            }
#pragma unroll
            for (int mt = 0; mt < 4; ++mt)
#pragma unroll
                for (int nt = 0; nt < 4; ++nt)
                    MMA_TF32(acc[mt][nt], af[mt], bf[nt]);
        }
    }

    // ---- epilogue ----
    const int wm = (wid >> 2) * 64;
    const int wn = (wid & 3) * 32;
#pragma unroll
    for (int mt = 0; mt < 4; ++mt) {
        int row0 = m0 + wm + mt * 16 + gid;
#pragma unroll
        for (int nt = 0; nt < 4; ++nt) {
            int col = n0 + wn + nt * 8 + 2 * tig;
            float b0 = biasP[col & 1023], b1 = biasP[(col + 1) & 1023];
            float2 r0 = make_float2(acc[mt][nt][0] + b0, acc[mt][nt][1] + b1);
            float2 r1 = make_float2(acc[mt][nt][2] + b0, acc[mt][nt][3] + b1);
            if (!QKV) {
                *(float2*)&C[(size_t)row0 * ldc + col]       = r0;
                *(float2*)&C[(size_t)(row0 + 8) * ldc + col] = r1;
            } else {
                int which = col >> 10, hh = (col >> 6) & 15, d = col & 63;
                int s0 = row0 >> 2, b0i = row0 & 3;
                int row1 = row0 + 8;
                int s1 = row1 >> 2, b1i = row1 & 3;
                size_t i0 = (((size_t)(which * BATCH + b0i) * NHEAD + hh) * S_LEN + s0) * DHEAD + d;
                size_t i1 = (((size_t)(which * BATCH + b1i) * NHEAD + hh) * S_LEN + s1) * DHEAD + d;
                *(float2*)&C[i0] = r0;
                *(float2*)&C[i1] = r1;
            }
        }
    }
}

// GEMM 1: qkv = {q|k|v} @ W{q|k|v} + b -> head-major scatter (reads weights directly)
__global__ void __launch_bounds__(256, 2) gemm_qkv_kernel(
    const float* __restrict__ q, const float* __restrict__ k, const float* __restrict__ v,
    const float* __restrict__ Wq, const float* __restrict__ Wk, const float* __restrict__ Wv,
    const float* __restrict__ bq, const float* __restrict__ bk, const float* __restrict__ bv) {
    int n0 = blockIdx.x * 128;
    int m0 = blockIdx.y * 128;
    const float* A     = (n0 < 1024) ? q  : (n0 < 2048) ? k  : v;
    const float* Wbase = (n0 < 1024) ? Wq : (n0 < 2048) ? Wk : Wv;
    const float* bias  = (n0 < 1024) ? bq : (n0 < 2048) ? bk : bv;
    int n = n0 + ((threadIdx.x & 31) << 2);
    // W element (d, n) = Wbase[h*65536 + d*64 + kk]; per-thread ptr, k-stride 64
    const float* Bthr = Wbase + ((size_t)((n >> 6) & 15) << 16) + (n & 63)
                      + (threadIdx.x >> 5) * 64;
    gemm_body<1>(A, Bthr, 64, bias, g_qkv, DMODEL, 0, m0, n0);
}

// GEMM 3: out[4096,1024] = g_concat @ Wo + bo
__global__ void __launch_bounds__(256, 2) gemm_out_kernel(
    const float* __restrict__ Wo, const float* __restrict__ bo, float* __restrict__ out) {
    int n0 = blockIdx.x * 128;
    int m0 = blockIdx.y * 128;
    const float* Bthr = Wo + (size_t)(threadIdx.x >> 5) * DMODEL + n0 + ((threadIdx.x & 31) << 2);
    gemm_body<0>(g_concat, Bthr, DMODEL, bo, out, DMODEL, DMODEL, m0, n0);
}

// ---------------- TF32 MMA flash attention (unchanged) ----------------
#define ATTN_SMEM_BYTES ((128 * 68 + 64 * 68 + 64 * 72 + 128 * 68 + 64) * 4)

__global__ void __launch_bounds__(256, 2) attn_kernel(const int* __restrict__ key_mask) {
    extern __shared__ unsigned sm[];
    unsigned* uQ = sm;
    unsigned* uK = uQ + 128 * 68;
    unsigned* uV = uK + 64 * 68;
    unsigned* uP = uV + 64 * 72;
    float* msk   = (float*)(uP + 128 * 68);

    const int b = blockIdx.z, h = blockIdx.y, i0 = blockIdx.x * 128;
    const int tid = threadIdx.x, lane = tid & 31, wid = tid >> 5;
    const int gid = lane >> 2, tig = lane & 3;
    const int wrow = wid * 16;

    const float* Qg = g_qkv + (((size_t)(0 * BATCH + b) * NHEAD + h) * S_LEN + i0) * DHEAD;
    const float* Kg = g_qkv + (((size_t)(1 * BATCH + b) * NHEAD + h) * S_LEN) * DHEAD;
    const float* Vg = g_qkv + (((size_t)(2 * BATCH + b) * NHEAD + h) * S_LEN) * DHEAD;

    {
        const float4* src = (const float4*)Qg;
#pragma unroll
        for (int r = 0; r < 8; ++r) {
            int f = tid + 256 * r;
            int i = f >> 4, d = (f & 15) << 2;
            float4 v = src[f];
            unsigned* dst = &uQ[i * 68 + d];
            dst[0] = f2tf(v.x); dst[1] = f2tf(v.y); dst[2] = f2tf(v.z); dst[3] = f2tf(v.w);
        }
    }

    float m0 = -1e30f, m1 = -1e30f, l0 = 0.f, l1 = 0.f;
    float o[8][4];
#pragma unroll
    for (int nt = 0; nt < 8; ++nt)
#pragma unroll
        for (int r = 0; r < 4; ++r) o[nt][r] = 0.f;

    for (int jt = 0; jt < S_LEN / 64; ++jt) {
        const int j0 = jt * 64;
        __syncthreads();
        {
            const float4* ks = (const float4*)(Kg + (size_t)j0 * DHEAD);
            const float4* vs = (const float4*)(Vg + (size_t)j0 * DHEAD);
#pragma unroll
            for (int r = 0; r < 4; ++r) {
                int f = tid + 256 * r;
                int j = f >> 4, d = (f & 15) << 2;
                float4 kv = ks[f];
                unsigned* kd = &uK[j * 68 + d];
                kd[0] = f2tf(kv.x); kd[1] = f2tf(kv.y); kd[2] = f2tf(kv.z); kd[3] = f2tf(kv.w);
                float4 vv = vs[f];
                unsigned* vd = &uV[j * 72 + d];
                vd[0] = f2tf(vv.x); vd[1] = f2tf(vv.y); vd[2] = f2tf(vv.z); vd[3] = f2tf(vv.w);
            }
            if (tid < 64)
                msk[tid] = key_mask[(j0 + tid) * BATCH + b] ? -1e18f : 0.f;
        }
        __syncthreads();

        float s[8][4];
#pragma unroll
        for (int nt = 0; nt < 8; ++nt)
#pragma unroll
            for (int r = 0; r < 4; ++r) s[nt][r] = 0.f;
#pragma unroll
        for (int kb = 0; kb < 64; kb += 8) {
            unsigned a[4];
            a[0] = uQ[(wrow + gid) * 68 + kb + tig];
            a[1] = uQ[(wrow + gid + 8) * 68 + kb + tig];
            a[2] = uQ[(wrow + gid) * 68 + kb + tig + 4];
            a[3] = uQ[(wrow + gid + 8) * 68 + kb + tig + 4];
#pragma unroll
            for (int nt = 0; nt < 8; ++nt) {
                unsigned bfr[2];
                bfr[0] = uK[(nt * 8 + gid) * 68 + kb + tig];
                bfr[1] = uK[(nt * 8 + gid) * 68 + kb + tig + 4];
                MMA_TF32(s[nt], a, bfr);
            }
        }

        float mx0 = -1e30f, mx1 = -1e30f;
#pragma unroll
        for (int nt = 0; nt < 8; ++nt) {
            float q0 = msk[nt * 8 + 2 * tig], q1 = msk[nt * 8 + 2 * tig + 1];
            s[nt][0] = fmaf(s[nt][0], 0.125f, q0);
            s[nt][1] = fmaf(s[nt][1], 0.125f, q1);
            s[nt][2] = fmaf(s[nt][2], 0.125f, q0);
            s[nt][3] = fmaf(s[nt][3], 0.125f, q1);
            mx0 = fmaxf(mx0, fmaxf(s[nt][0], s[nt][1]));
            mx1 = fmaxf(mx1, fmaxf(s[nt][2], s[nt][3]));
        }
        mx0 = fmaxf(mx0, __shfl_xor_sync(0xffffffffu, mx0, 1));
        mx0 = fmaxf(mx0, __shfl_xor_sync(0xffffffffu, mx0, 2));
        mx1 = fmaxf(mx1, __shfl_xor_sync(0xffffffffu, mx1, 1));
        mx1 = fmaxf(mx1, __shfl_xor_sync(0xffffffffu, mx1, 2));

        float mn0 = fmaxf(m0, mx0), mn1 = fmaxf(m1, mx1);
        float la0 = 0.f, la1 = 0.f;
        unsigned* p0row = &uP[(wrow + gid) * 68];
        unsigned* p1row = &uP[(wrow + gid + 8) * 68];
#pragma unroll
        for (int nt = 0; nt < 8; ++nt) {
            float p0 = __expf(s[nt][0] - mn0);
            float p1 = __expf(s[nt][1] - mn0);
            float p2 = __expf(s[nt][2] - mn1);
            float p3 = __expf(s[nt][3] - mn1);
            la0 += p0 + p1; la1 += p2 + p3;
            int c = nt * 8 + 2 * tig;
            p0row[c] = f2tf(p0); p0row[c + 1] = f2tf(p1);
            p1row[c] = f2tf(p2); p1row[c + 1] = f2tf(p3);
        }
        la0 += __shfl_xor_sync(0xffffffffu, la0, 1);
        la0 += __shfl_xor_sync(0xffffffffu, la0, 2);
        la1 += __shfl_xor_sync(0xffffffffu, la1, 1);
        la1 += __shfl_xor_sync(0xffffffffu, la1, 2);

        float al0 = __expf(m0 - mn0), al1 = __expf(m1 - mn1);
        l0 = l0 * al0 + la0;
        l1 = l1 * al1 + la1;
        m0 = mn0; m1 = mn1;
#pragma unroll
        for (int nt = 0; nt < 8; ++nt) {
            o[nt][0] *= al0; o[nt][1] *= al0;
            o[nt][2] *= al1; o[nt][3] *= al1;
        }
        __syncwarp();

#pragma unroll
        for (int kb = 0; kb < 64; kb += 8) {
            unsigned a[4];
            a[0] = uP[(wrow + gid) * 68 + kb + tig];
            a[1] = uP[(wrow + gid + 8) * 68 + kb + tig];
            a[2] = uP[(wrow + gid) * 68 + kb + tig + 4];
            a[3] = uP[(wrow + gid + 8) * 68 + kb + tig + 4];
#pragma unroll
            for (int nt = 0; nt < 8; ++nt) {
                unsigned bfr[2];
                bfr[0] = uV[(kb + tig) * 72 + nt * 8 + gid];
                bfr[1] = uV[(kb + tig + 4) * 72 + nt * 8 + gid];
                MMA_TF32(o[nt], a, bfr);
            }
        }
    }

    float inv0 = 1.f / l0, inv1 = 1.f / l1;
    int r0 = i0 + wrow + gid;
#pragma unroll
    for (int nt = 0; nt < 8; ++nt) {
        int col = h * 64 + nt * 8 + 2 * tig;
        *(float2*)&g_concat[(size_t)(r0 * BATCH + b) * DMODEL + col] =
            make_float2(o[nt][0] * inv0, o[nt][1] * inv0);
        *(float2*)&g_concat[(size_t)((r0 + 8) * BATCH + b) * DMODEL + col] =
            make_float2(o[nt][2] * inv1, o[nt][3] * inv1);
    }
}

// ---------------- entry point ----------------
extern "C" void kernel_launch(void* const* d_in, const int* in_sizes, int n_in,
                              void* d_out, int out_size) {
    const float* query    = (const float*)d_in[0];
    const float* key      = (const float*)d_in[1];
    const float* value    = (const float*)d_in[2];
    const int*   key_mask = (const int*)  d_in[3];
    const float* Wq = (const float*)d_in[4];
    const float* bq = (const float*)d_in[5];
    const float* Wk = (const float*)d_in[6];
    const float* bk = (const float*)d_in[7];
    const float* Wv = (const float*)d_in[8];
    const float* bv = (const float*)d_in[9];
    const float* Wo = (const float*)d_in[10];
    const float* bo = (const float*)d_in[11];
    float* out = (float*)d_out;

    cudaFuncSetAttribute(attn_kernel, cudaFuncAttributeMaxDynamicSharedMemorySize,
                         ATTN_SMEM_BYTES);
    cudaFuncSetAttribute(gemm_qkv_kernel, cudaFuncAttributeMaxDynamicSharedMemorySize,
                         GEMM_SMEM_BYTES);
    cudaFuncSetAttribute(gemm_out_kernel, cudaFuncAttributeMaxDynamicSharedMemorySize,
                         GEMM_SMEM_BYTES);

    gemm_qkv_kernel<<<dim3(3 * DMODEL / 128, S_LEN * BATCH / 128), 256, GEMM_SMEM_BYTES>>>(
        query, key, value, Wq, Wk, Wv, bq, bk, bv);
    attn_kernel<<<dim3(S_LEN / 128, NHEAD, BATCH), 256, ATTN_SMEM_BYTES>>>(key_mask);
    gemm_out_kernel<<<dim3(DMODEL / 128, S_LEN * BATCH / 128), 256, GEMM_SMEM_BYTES>>>(Wo, bo, out);
}

// round 8
// speedup vs baseline: 1.9375x; 1.9375x over previous
#include <cuda_runtime.h>
#include <math.h>

#define S_LEN  1024
#define BATCH  4
#define DMODEL 1024
#define NHEAD  16
#define DHEAD  64
#define NIN    (S_LEN * BATCH * DMODEL)   // 4M elements per input tensor

// ---------------- device scratch (tf32 bit patterns stored as u32) ----------------
__device__ unsigned g_in[3 * NIN];                  // converted query/key/value
__device__ unsigned g_Wt[DMODEL * 3 * DMODEL];      // packed qkv weights [d][which*1024+h*64+kk]
__device__ unsigned g_Wo[DMODEL * DMODEL];          // converted Wo
__device__ float    g_bias[3 * DMODEL];             // packed qkv bias (f32)
// head-major qkv (tf32 bits): (((which*BATCH+b)*NHEAD+h)*S_LEN+s)*DHEAD+d
__device__ unsigned g_qkv[3 * BATCH * NHEAD * S_LEN * DHEAD];
__device__ unsigned g_concat[S_LEN * BATCH * DMODEL];  // [s*B+b][h*64+d] tf32 bits

// ---------------- helpers ----------------
__device__ __forceinline__ unsigned f2tf(float f) {
    unsigned u;
    asm("cvt.rna.tf32.f32 %0, %1;" : "=r"(u) : "f"(f));
    return u;
}

#define MMA_TF32(d, a, b)                                                        \
    asm volatile(                                                                \
        "mma.sync.aligned.m16n8k8.row.col.f32.tf32.tf32.f32 "                    \
        "{%0,%1,%2,%3}, {%4,%5,%6,%7}, {%8,%9}, {%0,%1,%2,%3};"                  \
        : "+f"((d)[0]), "+f"((d)[1]), "+f"((d)[2]), "+f"((d)[3])                 \
        : "r"((a)[0]), "r"((a)[1]), "r"((a)[2]), "r"((a)[3]),                    \
          "r"((b)[0]), "r"((b)[1]))

// ---------------- prep: convert inputs + pack/convert weights to tf32 ----------------
__global__ void prep_kernel(const float* __restrict__ q, const float* __restrict__ k,
                            const float* __restrict__ v,
                            const float* __restrict__ Wq, const float* __restrict__ Wk,
                            const float* __restrict__ Wv,
                            const float* __restrict__ bq, const float* __restrict__ bk,
                            const float* __restrict__ bv, const float* __restrict__ Wo) {
    int t = blockIdx.x * blockDim.x + threadIdx.x;
    if (t < NIN) {
        g_in[t]           = f2tf(q[t]);
        g_in[NIN + t]     = f2tf(k[t]);
        g_in[2 * NIN + t] = f2tf(v[t]);
    }
    const int NW = DMODEL * DMODEL;
    if (t < NW) {
        int d = t >> 10, r = t & 1023;                    // r = h*64+kk
        int src = ((r >> 6) << 16) + (d << 6) + (r & 63); // h*65536 + d*64 + kk
        g_Wt[d * 3072 + r]        = f2tf(Wq[src]);
        g_Wt[d * 3072 + 1024 + r] = f2tf(Wk[src]);
        g_Wt[d * 3072 + 2048 + r] = f2tf(Wv[src]);
        g_Wo[t] = f2tf(Wo[t]);
    }
    if (t < 3 * DMODEL) {
        const float* bb = (t < 1024) ? bq : (t < 2048) ? bk : bv;
        g_bias[t] = bb[t & 1023];
    }
}

// ---------------- TF32 GEMM: 128x128x32 tile, 8 warps, static smem, pure-copy staging ----------------
// REMAP=1: scatter into head-major g_qkv (tf32 bits). REMAP=0: plain f32 store.
template<int REMAP>
__device__ __forceinline__ void gemm_body(
    const unsigned* __restrict__ A, int lda,
    const unsigned* __restrict__ B, int ldb,
    const float* __restrict__ bias, void* __restrict__ Cout,
    int ldc, int m0, int n0)
{
    __shared__ unsigned As[128][36];   // [m][k] pad 4
    __shared__ unsigned Bs[32][136];   // [k][n] pad 8

    const int tid  = threadIdx.x;
    const int lane = tid & 31;
    const int wid  = tid >> 5;
    const int gid  = lane >> 2;
    const int tig  = lane & 3;
    const int wm   = (wid >> 2) * 64;
    const int wn   = (wid & 3) * 32;

    float acc[4][4][4];
#pragma unroll
    for (int mt = 0; mt < 4; ++mt)
#pragma unroll
        for (int nt = 0; nt < 4; ++nt)
#pragma unroll
            for (int r = 0; r < 4; ++r) acc[mt][nt][r] = 0.f;

    const int arow = tid >> 3;           // 0..31
    const int acol = (tid & 7) << 2;     // 0..28
    const int brow = tid >> 5;           // 0..7
    const int bcol = (tid & 31) << 2;    // 0..124

    const unsigned* Ap = A + (size_t)(m0 + arow) * lda + acol;
    const unsigned* Bp = B + (size_t)brow * ldb + n0 + bcol;

    uint4 ag[4], bg[4];
#pragma unroll
    for (int r = 0; r < 4; ++r) ag[r] = *(const uint4*)(Ap + (size_t)(32 * r) * lda);
#pragma unroll
    for (int r = 0; r < 4; ++r) bg[r] = *(const uint4*)(Bp + (size_t)(8 * r) * ldb);

    for (int k0 = 0; k0 < DMODEL; k0 += 32) {
        __syncthreads();
#pragma unroll
        for (int r = 0; r < 4; ++r)
            *(uint4*)&As[arow + 32 * r][acol] = ag[r];
#pragma unroll
        for (int r = 0; r < 4; ++r)
            *(uint4*)&Bs[brow + 8 * r][bcol] = bg[r];
        __syncthreads();

        if (k0 + 32 < DMODEL) {
#pragma unroll
            for (int r = 0; r < 4; ++r)
                ag[r] = *(const uint4*)(Ap + (size_t)(32 * r) * lda + (k0 + 32));
#pragma unroll
            for (int r = 0; r < 4; ++r)
                bg[r] = *(const uint4*)(Bp + (size_t)(k0 + 32 + 8 * r) * ldb);
        }

#pragma unroll
        for (int kb = 0; kb < 4; ++kb) {
            const int kk = kb * 8;
            unsigned af[4][4], bf[4][2];
#pragma unroll
            for (int mt = 0; mt < 4; ++mt) {
                int r = wm + mt * 16 + gid;
                af[mt][0] = As[r][kk + tig];
                af[mt][1] = As[r + 8][kk + tig];
                af[mt][2] = As[r][kk + tig + 4];
                af[mt][3] = As[r + 8][kk + tig + 4];
            }
#pragma unroll
            for (int nt = 0; nt < 4; ++nt) {
                int c = wn + nt * 8 + gid;
                bf[nt][0] = Bs[kk + tig][c];
                bf[nt][1] = Bs[kk + tig + 4][c];
            }
#pragma unroll
            for (int mt = 0; mt < 4; ++mt)
#pragma unroll
                for (int nt = 0; nt < 4; ++nt)
                    MMA_TF32(acc[mt][nt], af[mt], bf[nt]);
        }
    }

    // ---- epilogue ----
#pragma unroll
    for (int mt = 0; mt < 4; ++mt) {
        int row0 = m0 + wm + mt * 16 + gid;
#pragma unroll
        for (int nt = 0; nt < 4; ++nt) {
            int col = n0 + wn + nt * 8 + 2 * tig;
            float b0 = bias[col], b1 = bias[col + 1];
            float x0 = acc[mt][nt][0] + b0, y0 = acc[mt][nt][1] + b1;
            float x1 = acc[mt][nt][2] + b0, y1 = acc[mt][nt][3] + b1;
            if (!REMAP) {
                float* C = (float*)Cout;
                *(float2*)&C[(size_t)row0 * ldc + col]       = make_float2(x0, y0);
                *(float2*)&C[(size_t)(row0 + 8) * ldc + col] = make_float2(x1, y1);
            } else {
                unsigned* C = (unsigned*)Cout;
                int which = col >> 10, hh = (col >> 6) & 15, d = col & 63;
                int s0 = row0 >> 2, b0i = row0 & 3;
                int row1 = row0 + 8;
                int s1 = row1 >> 2, b1i = row1 & 3;
                size_t i0 = (((size_t)(which * BATCH + b0i) * NHEAD + hh) * S_LEN + s0) * DHEAD + d;
                size_t i1 = (((size_t)(which * BATCH + b1i) * NHEAD + hh) * S_LEN + s1) * DHEAD + d;
                *(uint2*)&C[i0] = make_uint2(f2tf(x0), f2tf(y0));
                *(uint2*)&C[i1] = make_uint2(f2tf(x1), f2tf(y1));
            }
        }
    }
}

// GEMM 1: qkv = conv{q|k|v} @ g_Wt + g_bias -> head-major tf32 scatter
__global__ void __launch_bounds__(256, 2) gemm_qkv_kernel() {
    int n0 = blockIdx.x * 128;
    int m0 = blockIdx.y * 128;
    const unsigned* A = g_in + (size_t)(n0 >> 10) * NIN;
    gemm_body<1>(A, DMODEL, g_Wt, 3 * DMODEL, g_bias, g_qkv, 0, m0, n0);
}

// GEMM 3: out[4096,1024] = g_concat @ g_Wo + bo (full f32 output)
__global__ void __launch_bounds__(256, 2) gemm_out_kernel(
    const float* __restrict__ bo, float* __restrict__ out) {
    int n0 = blockIdx.x * 128;
    int m0 = blockIdx.y * 128;
    gemm_body<0>(g_concat, DMODEL, g_Wo, DMODEL, bo, out, DMODEL, m0, n0);
}

// ---------------- TF32 MMA flash attention (tf32-bit inputs, raw-copy staging) ----------------
#define ATTN_SMEM_BYTES ((128 * 68 + 64 * 68 + 64 * 72 + 128 * 68 + 64) * 4)

__global__ void __launch_bounds__(256, 2) attn_kernel(const int* __restrict__ key_mask) {
    extern __shared__ unsigned sm[];
    unsigned* uQ = sm;                       // [128][68]
    unsigned* uK = uQ + 128 * 68;            // [64][68]
    unsigned* uV = uK + 64 * 68;             // [64][72]
    unsigned* uP = uV + 64 * 72;             // [128][68]
    float* msk   = (float*)(uP + 128 * 68);  // [64]

    const int b = blockIdx.z, h = blockIdx.y, i0 = blockIdx.x * 128;
    const int tid = threadIdx.x, lane = tid & 31, wid = tid >> 5;
    const int gid = lane >> 2, tig = lane & 3;
    const int wrow = wid * 16;

    const unsigned* Qg = g_qkv + (((size_t)(0 * BATCH + b) * NHEAD + h) * S_LEN + i0) * DHEAD;
    const unsigned* Kg = g_qkv + (((size_t)(1 * BATCH + b) * NHEAD + h) * S_LEN) * DHEAD;
    const unsigned* Vg = g_qkv + (((size_t)(2 * BATCH + b) * NHEAD + h) * S_LEN) * DHEAD;

    {
        const uint4* src = (const uint4*)Qg;
#pragma unroll
        for (int r = 0; r < 8; ++r) {
            int f = tid + 256 * r;
            int i = f >> 4, d = (f & 15) << 2;
            uint4 v = src[f];
            unsigned* dst = &uQ[i * 68 + d];
            dst[0] = v.x; dst[1] = v.y; dst[2] = v.z; dst[3] = v.w;
        }
    }

    float m0 = -1e30f, m1 = -1e30f, l0 = 0.f, l1 = 0.f;
    float o[8][4];
#pragma unroll
    for (int nt = 0; nt < 8; ++nt)
#pragma unroll
        for (int r = 0; r < 4; ++r) o[nt][r] = 0.f;

    for (int jt = 0; jt < S_LEN / 64; ++jt) {
        const int j0 = jt * 64;
        __syncthreads();
        {
            const uint4* ks = (const uint4*)(Kg + (size_t)j0 * DHEAD);
            const uint4* vs = (const uint4*)(Vg + (size_t)j0 * DHEAD);
#pragma unroll
            for (int r = 0; r < 4; ++r) {
                int f = tid + 256 * r;
                int j = f >> 4, d = (f & 15) << 2;
                uint4 kv = ks[f];
                unsigned* kd = &uK[j * 68 + d];
                kd[0] = kv.x; kd[1] = kv.y; kd[2] = kv.z; kd[3] = kv.w;
                uint4 vv = vs[f];
                unsigned* vd = &uV[j * 72 + d];
                vd[0] = vv.x; vd[1] = vv.y; vd[2] = vv.z; vd[3] = vv.w;
            }
            if (tid < 64)
                msk[tid] = key_mask[(j0 + tid) * BATCH + b] ? -1e18f : 0.f;
        }
        __syncthreads();

        float s[8][4];
#pragma unroll
        for (int nt = 0; nt < 8; ++nt)
#pragma unroll
            for (int r = 0; r < 4; ++r) s[nt][r] = 0.f;
#pragma unroll
        for (int kb = 0; kb < 64; kb += 8) {
            unsigned a[4];
            a[0] = uQ[(wrow + gid) * 68 + kb + tig];
            a[1] = uQ[(wrow + gid + 8) * 68 + kb + tig];
            a[2] = uQ[(wrow + gid) * 68 + kb + tig + 4];
            a[3] = uQ[(wrow + gid + 8) * 68 + kb + tig + 4];
#pragma unroll
            for (int nt = 0; nt < 8; ++nt) {
                unsigned bfr[2];
                bfr[0] = uK[(nt * 8 + gid) * 68 + kb + tig];
                bfr[1] = uK[(nt * 8 + gid) * 68 + kb + tig + 4];
                MMA_TF32(s[nt], a, bfr);
            }
        }

        float mx0 = -1e30f, mx1 = -1e30f;
#pragma unroll
        for (int nt = 0; nt < 8; ++nt) {
            float q0 = msk[nt * 8 + 2 * tig], q1 = msk[nt * 8 + 2 * tig + 1];
            s[nt][0] = fmaf(s[nt][0], 0.125f, q0);
            s[nt][1] = fmaf(s[nt][1], 0.125f, q1);
            s[nt][2] = fmaf(s[nt][2], 0.125f, q0);
            s[nt][3] = fmaf(s[nt][3], 0.125f, q1);
            mx0 = fmaxf(mx0, fmaxf(s[nt][0], s[nt][1]));
            mx1 = fmaxf(mx1, fmaxf(s[nt][2], s[nt][3]));
        }
        mx0 = fmaxf(mx0, __shfl_xor_sync(0xffffffffu, mx0, 1));
        mx0 = fmaxf(mx0, __shfl_xor_sync(0xffffffffu, mx0, 2));
        mx1 = fmaxf(mx1, __shfl_xor_sync(0xffffffffu, mx1, 1));
        mx1 = fmaxf(mx1, __shfl_xor_sync(0xffffffffu, mx1, 2));

        float mn0 = fmaxf(m0, mx0), mn1 = fmaxf(m1, mx1);
        float la0 = 0.f, la1 = 0.f;
        unsigned* p0row = &uP[(wrow + gid) * 68];
        unsigned* p1row = &uP[(wrow + gid + 8) * 68];
#pragma unroll
        for (int nt = 0; nt < 8; ++nt) {
            float p0 = __expf(s[nt][0] - mn0);
            float p1 = __expf(s[nt][1] - mn0);
            float p2 = __expf(s[nt][2] - mn1);
            float p3 = __expf(s[nt][3] - mn1);
            la0 += p0 + p1; la1 += p2 + p3;
            int c = nt * 8 + 2 * tig;
            p0row[c] = f2tf(p0); p0row[c + 1] = f2tf(p1);
            p1row[c] = f2tf(p2); p1row[c + 1] = f2tf(p3);
        }
        la0 += __shfl_xor_sync(0xffffffffu, la0, 1);
        la0 += __shfl_xor_sync(0xffffffffu, la0, 2);
        la1 += __shfl_xor_sync(0xffffffffu, la1, 1);
        la1 += __shfl_xor_sync(0xffffffffu, la1, 2);

        float al0 = __expf(m0 - mn0), al1 = __expf(m1 - mn1);
        l0 = l0 * al0 + la0;
        l1 = l1 * al1 + la1;
        m0 = mn0; m1 = mn1;
#pragma unroll
        for (int nt = 0; nt < 8; ++nt) {
            o[nt][0] *= al0; o[nt][1] *= al0;
            o[nt][2] *= al1; o[nt][3] *= al1;
        }
        __syncwarp();

#pragma unroll
        for (int kb = 0; kb < 64; kb += 8) {
            unsigned a[4];
            a[0] = uP[(wrow + gid) * 68 + kb + tig];
            a[1] = uP[(wrow + gid + 8) * 68 + kb + tig];
            a[2] = uP[(wrow + gid) * 68 + kb + tig + 4];
            a[3] = uP[(wrow + gid + 8) * 68 + kb + tig + 4];
#pragma unroll
            for (int nt = 0; nt < 8; ++nt) {
                unsigned bfr[2];
                bfr[0] = uV[(kb + tig) * 72 + nt * 8 + gid];
                bfr[1] = uV[(kb + tig + 4) * 72 + nt * 8 + gid];
                MMA_TF32(o[nt], a, bfr);
            }
        }
    }

    float inv0 = 1.f / l0, inv1 = 1.f / l1;
    int r0 = i0 + wrow + gid;
#pragma unroll
    for (int nt = 0; nt < 8; ++nt) {
        int col = h * 64 + nt * 8 + 2 * tig;
        *(uint2*)&g_concat[(size_t)(r0 * BATCH + b) * DMODEL + col] =
            make_uint2(f2tf(o[nt][0] * inv0), f2tf(o[nt][1] * inv0));
        *(uint2*)&g_concat[(size_t)((r0 + 8) * BATCH + b) * DMODEL + col] =
            make_uint2(f2tf(o[nt][2] * inv1), f2tf(o[nt][3] * inv1));
    }
}

// ---------------- entry point ----------------
extern "C" void kernel_launch(void* const* d_in, const int* in_sizes, int n_in,
                              void* d_out, int out_size) {
    const float* query    = (const float*)d_in[0];
    const float* key      = (const float*)d_in[1];
    const float* value    = (const float*)d_in[2];
    const int*   key_mask = (const int*)  d_in[3];
    const float* Wq = (const float*)d_in[4];
    const float* bq = (const float*)d_in[5];
    const float* Wk = (const float*)d_in[6];
    const float* bk = (const float*)d_in[7];
    const float* Wv = (const float*)d_in[8];
    const float* bv = (const float*)d_in[9];
    const float* Wo = (const float*)d_in[10];
    const float* bo = (const float*)d_in[11];
    float* out = (float*)d_out;

    cudaFuncSetAttribute(attn_kernel, cudaFuncAttributeMaxDynamicSharedMemorySize,
                         ATTN_SMEM_BYTES);

    prep_kernel<<<(NIN + 255) / 256, 256>>>(query, key, value, Wq, Wk, Wv, bq, bk, bv, Wo);
    gemm_qkv_kernel<<<dim3(3 * DMODEL / 128, S_LEN * BATCH / 128), 256>>>();
    attn_kernel<<<dim3(S_LEN / 128, NHEAD, BATCH), 256, ATTN_SMEM_BYTES>>>(key_mask);
    gemm_out_kernel<<<dim3(DMODEL / 128, S_LEN * BATCH / 128), 256>>>(bo, out);
}

// round 9
// speedup vs baseline: 3.1273x; 1.6141x over previous
#include <cuda_runtime.h>
#include <cuda_fp16.h>
#include <math.h>

#define S_LEN  1024
#define BATCH  4
#define DMODEL 1024
#define NHEAD  16
#define DHEAD  64
#define NIN    (S_LEN * BATCH * DMODEL)
#define NWRD   (NIN / 2)                 // packed half2 words per input tensor

// ---------------- device scratch (packed half2 words) ----------------
__device__ unsigned g_in[3 * NWRD];                 // q/k/v packed along dmodel
__device__ unsigned g_Wt[512 * 3 * DMODEL];         // qkv weights [kp][which*1024+h*64+kk]
__device__ unsigned g_Wo[512 * DMODEL];             // Wo [kp][n]
__device__ float    g_bias[3 * DMODEL];
// head-major qkv words: (((which*4+b)*16+h)*1024 + s)*32 + dp
__device__ unsigned g_qkv[3 * BATCH * NHEAD * S_LEN * 32];
__device__ unsigned g_concat[S_LEN * BATCH * 512];  // [s*B+b][h*32+dp]

// ---------------- helpers ----------------
__device__ __forceinline__ unsigned pack2h(float a, float b) {
    __half2 h = __floats2half2_rn(a, b);
    return *(unsigned*)&h;
}

#define MMA_F16(d, a, b)                                                         \
    asm volatile(                                                                \
        "mma.sync.aligned.m16n8k16.row.col.f32.f16.f16.f32 "                     \
        "{%0,%1,%2,%3}, {%4,%5,%6,%7}, {%8,%9}, {%0,%1,%2,%3};"                  \
        : "+f"((d)[0]), "+f"((d)[1]), "+f"((d)[2]), "+f"((d)[3])                 \
        : "r"((a)[0]), "r"((a)[1]), "r"((a)[2]), "r"((a)[3]),                    \
          "r"((b)[0]), "r"((b)[1]))

// ---------------- prep: convert + pack everything to half2 words ----------------
__global__ void prep_kernel(const float* __restrict__ q, const float* __restrict__ k,
                            const float* __restrict__ v,
                            const float* __restrict__ Wq, const float* __restrict__ Wk,
                            const float* __restrict__ Wv,
                            const float* __restrict__ bq, const float* __restrict__ bk,
                            const float* __restrict__ bv, const float* __restrict__ Wo) {
    int t = blockIdx.x * blockDim.x + threadIdx.x;
    if (t < NWRD) {
        g_in[t]            = pack2h(q[2 * t], q[2 * t + 1]);
        g_in[NWRD + t]     = pack2h(k[2 * t], k[2 * t + 1]);
        g_in[2 * NWRD + t] = pack2h(v[2 * t], v[2 * t + 1]);
    }
    const int NWT = 512 * 3 * DMODEL;       // 1.5M
    if (t < NWT) {
        int kp = t / 3072, n = t - kp * 3072;
        int which = n >> 10, r = n & 1023;
        int h = r >> 6, kk = r & 63;
        const float* W = (which == 0) ? Wq : (which == 1) ? Wk : Wv;
        int base = (h * 1024 + 2 * kp) * 64 + kk;
        g_Wt[t] = pack2h(W[base], W[base + 64]);
    }
    const int NWO = 512 * DMODEL;
    if (t < NWO) {
        int kp = t >> 10, n = t & 1023;
        g_Wo[t] = pack2h(Wo[2 * kp * 1024 + n], Wo[(2 * kp + 1) * 1024 + n]);
    }
    if (t < 3 * DMODEL) {
        const float* bb = (t < 1024) ? bq : (t < 2048) ? bk : bv;
        g_bias[t] = bb[t & 1023];
    }
}

// ---------------- FP16 GEMM: 128x128x64 tile (32 words k), 8 warps ----------------
template<int REMAP>
__device__ __forceinline__ void gemm_body(
    const unsigned* __restrict__ A, int lda,       // words, row-major [m][kp]
    const unsigned* __restrict__ B, int ldb,       // words, [kp][n]
    const float* __restrict__ bias, void* __restrict__ Cout,
    int ldc, int m0, int n0)
{
    __shared__ unsigned As[128 * 36];   // [m][kp] pad 4 (stride 36 % 32 == 4)
    __shared__ unsigned Bs[32 * 132];   // [kp][n] pad 4 (stride 132 % 32 == 4)

    const int tid  = threadIdx.x;
    const int lane = tid & 31;
    const int wid  = tid >> 5;
    const int gid  = lane >> 2;
    const int tig  = lane & 3;
    const int wm   = (wid >> 2) * 64;
    const int wn   = (wid & 3) * 32;

    float acc[4][4][4];
#pragma unroll
    for (int mt = 0; mt < 4; ++mt)
#pragma unroll
        for (int nt = 0; nt < 4; ++nt)
#pragma unroll
            for (int r = 0; r < 4; ++r) acc[mt][nt][r] = 0.f;

    const int arow = tid >> 2;           // 0..63 (and +64)
    const int acol = (tid & 3) << 3;     // 0,8,16,24 (and +4)
    const int brow = tid >> 5;           // 0..7 (and +8,+16,+24)
    const int bcol = (tid & 31) << 2;    // 0..124

    const unsigned* Ap = A + (size_t)(m0 + arow) * lda + acol;
    const unsigned* Bp = B + (size_t)brow * ldb + n0 + bcol;

    uint4 ag[4], bg[4];
#pragma unroll
    for (int r = 0; r < 2; ++r) {
        ag[2 * r]     = *(const uint4*)(Ap + (size_t)(64 * r) * lda);
        ag[2 * r + 1] = *(const uint4*)(Ap + (size_t)(64 * r) * lda + 4);
    }
#pragma unroll
    for (int r = 0; r < 4; ++r)
        bg[r] = *(const uint4*)(Bp + (size_t)(8 * r) * ldb);

    for (int k0 = 0; k0 < 512; k0 += 32) {   // 16 k-tiles of 32 words (64 halves)
        __syncthreads();
#pragma unroll
        for (int r = 0; r < 2; ++r) {
            *(uint4*)&As[(arow + 64 * r) * 36 + acol]     = ag[2 * r];
            *(uint4*)&As[(arow + 64 * r) * 36 + acol + 4] = ag[2 * r + 1];
        }
#pragma unroll
        for (int r = 0; r < 4; ++r)
            *(uint4*)&Bs[(brow + 8 * r) * 132 + bcol] = bg[r];
        __syncthreads();

        if (k0 + 32 < 512) {
#pragma unroll
            for (int r = 0; r < 2; ++r) {
                ag[2 * r]     = *(const uint4*)(Ap + (size_t)(64 * r) * lda + k0 + 32);
                ag[2 * r + 1] = *(const uint4*)(Ap + (size_t)(64 * r) * lda + k0 + 36);
            }
#pragma unroll
            for (int r = 0; r < 4; ++r)
                bg[r] = *(const uint4*)(Bp + (size_t)(k0 + 32 + 8 * r) * ldb);
        }

#pragma unroll
        for (int kb = 0; kb < 4; ++kb) {
            const int kk = kb * 8;
            unsigned af[4][4], bf[4][2];
#pragma unroll
            for (int mt = 0; mt < 4; ++mt) {
                int r = wm + mt * 16 + gid;
                af[mt][0] = As[r * 36 + kk + tig];
                af[mt][1] = As[(r + 8) * 36 + kk + tig];
                af[mt][2] = As[r * 36 + kk + tig + 4];
                af[mt][3] = As[(r + 8) * 36 + kk + tig + 4];
            }
#pragma unroll
            for (int nt = 0; nt < 4; ++nt) {
                int c = wn + nt * 8 + gid;
                bf[nt][0] = Bs[(kk + tig) * 132 + c];
                bf[nt][1] = Bs[(kk + tig + 4) * 132 + c];
            }
#pragma unroll
            for (int mt = 0; mt < 4; ++mt)
#pragma unroll
                for (int nt = 0; nt < 4; ++nt)
                    MMA_F16(acc[mt][nt], af[mt], bf[nt]);
        }
    }

    // ---- epilogue ----
#pragma unroll
    for (int mt = 0; mt < 4; ++mt) {
        int row0 = m0 + wm + mt * 16 + gid;
#pragma unroll
        for (int nt = 0; nt < 4; ++nt) {
            int col = n0 + wn + nt * 8 + 2 * tig;
            float b0 = bias[col], b1 = bias[col + 1];
            float x0 = acc[mt][nt][0] + b0, y0 = acc[mt][nt][1] + b1;
            float x1 = acc[mt][nt][2] + b0, y1 = acc[mt][nt][3] + b1;
            if (!REMAP) {
                float* C = (float*)Cout;
                *(float2*)&C[(size_t)row0 * ldc + col]       = make_float2(x0, y0);
                *(float2*)&C[(size_t)(row0 + 8) * ldc + col] = make_float2(x1, y1);
            } else {
                unsigned* C = (unsigned*)Cout;
                int which = col >> 10, hh = (col >> 6) & 15, dp = (col & 63) >> 1;
                int s0 = row0 >> 2, b0i = row0 & 3;
                int s1 = (row0 + 8) >> 2, b1i = (row0 + 8) & 3;
                C[((((size_t)(which * 4 + b0i) * 16 + hh) * 1024 + s0) * 32) + dp] = pack2h(x0, y0);
                C[((((size_t)(which * 4 + b1i) * 16 + hh) * 1024 + s1) * 32) + dp] = pack2h(x1, y1);
            }
        }
    }
}

__global__ void __launch_bounds__(256, 2) gemm_qkv_kernel() {
    int n0 = blockIdx.x * 128;
    int m0 = blockIdx.y * 128;
    const unsigned* A = g_in + (size_t)(n0 >> 10) * NWRD;
    gemm_body<1>(A, 512, g_Wt, 3 * DMODEL, g_bias, g_qkv, 0, m0, n0);
}

__global__ void __launch_bounds__(256, 2) gemm_out_kernel(
    const float* __restrict__ bo, float* __restrict__ out) {
    int n0 = blockIdx.x * 128;
    int m0 = blockIdx.y * 128;
    gemm_body<0>(g_concat, 512, g_Wo, DMODEL, bo, out, DMODEL, m0, n0);
}

// ---------------- FP16 MMA flash attention ----------------
// smem words: uQ[128][36], uK[64][36], uV[32][68], uP[128][36], msk[64]
#define ATTN_SMEM_BYTES ((128 * 36 + 64 * 36 + 32 * 68 + 128 * 36 + 64) * 4)

__global__ void __launch_bounds__(256, 2) attn_kernel(const int* __restrict__ key_mask) {
    extern __shared__ unsigned sm[];
    unsigned* uQ = sm;                        // [128][36] A-operand, packed d
    unsigned* uK = uQ + 128 * 36;             // [64][36]  B-operand [n=j][kp=dp]
    unsigned* uV = uK + 64 * 36;              // [32][68]  B-operand [kp=jp][n=d]
    unsigned* uP = uV + 32 * 68;              // [128][36] A-operand, packed j
    float* msk   = (float*)(uP + 128 * 36);   // [64]

    const int b = blockIdx.z, h = blockIdx.y, i0 = blockIdx.x * 128;
    const int tid = threadIdx.x, lane = tid & 31, wid = tid >> 5;
    const int gid = lane >> 2, tig = lane & 3;
    const int wrow = wid * 16;

    const unsigned* Qg = g_qkv + (((size_t)(0 * 4 + b) * 16 + h) * 1024 + i0) * 32;
    const unsigned* Kg = g_qkv + (((size_t)(1 * 4 + b) * 16 + h) * 1024) * 32;
    const unsigned* Vg = g_qkv + (((size_t)(2 * 4 + b) * 16 + h) * 1024) * 32;

    // ---- stage Q (128 x 32 words) ----
    {
        const uint4* src = (const uint4*)Qg;
#pragma unroll
        for (int r = 0; r < 4; ++r) {
            int idx = tid + 256 * r;
            int i = idx >> 3, c4 = (idx & 7) << 2;
            *(uint4*)&uQ[i * 36 + c4] = src[idx];
        }
    }

    float m0 = -1e30f, m1 = -1e30f, l0 = 0.f, l1 = 0.f;
    float o[8][4];
#pragma unroll
    for (int nt = 0; nt < 8; ++nt)
#pragma unroll
        for (int r = 0; r < 4; ++r) o[nt][r] = 0.f;

    for (int jt = 0; jt < S_LEN / 64; ++jt) {
        const int j0 = jt * 64;
        __syncthreads();
        {
            // K: 64 x 32 words, natural layout
            const uint4* ks = (const uint4*)(Kg + (size_t)j0 * 32);
#pragma unroll
            for (int r = 0; r < 2; ++r) {
                int idx = tid + 256 * r;
                int j = idx >> 3, c4 = (idx & 7) << 2;
                *(uint4*)&uK[j * 36 + c4] = ks[idx];
            }
            // V: pack along j  (word(jp,d) = (V[2jp][d], V[2jp+1][d]))
            const uint4* vs = (const uint4*)(Vg + (size_t)j0 * 32);
            int jp = tid >> 3, c = tid & 7;        // c indexes uint4 within a 32-word row
            uint4 r0 = vs[(2 * jp) * 8 + c];
            uint4 r1 = vs[(2 * jp + 1) * 8 + c];
            uint4 o0, o1;
            o0.x = __byte_perm(r0.x, r1.x, 0x5410); o0.y = __byte_perm(r0.x, r1.x, 0x7632);
            o0.z = __byte_perm(r0.y, r1.y, 0x5410); o0.w = __byte_perm(r0.y, r1.y, 0x7632);
            o1.x = __byte_perm(r0.z, r1.z, 0x5410); o1.y = __byte_perm(r0.z, r1.z, 0x7632);
            o1.z = __byte_perm(r0.w, r1.w, 0x5410); o1.w = __byte_perm(r0.w, r1.w, 0x7632);
            *(uint4*)&uV[jp * 68 + c * 8]     = o0;
            *(uint4*)&uV[jp * 68 + c * 8 + 4] = o1;

            if (tid < 64)
                msk[tid] = key_mask[(j0 + tid) * BATCH + b] ? -1e18f : 0.f;
        }
        __syncthreads();

        // ---- S = Q @ K^T (16x64 per warp, 4 k-steps) ----
        float s[8][4];
#pragma unroll
        for (int nt = 0; nt < 8; ++nt)
#pragma unroll
            for (int r = 0; r < 4; ++r) s[nt][r] = 0.f;
#pragma unroll
        for (int kb = 0; kb < 4; ++kb) {
            const int kk = kb * 8;
            unsigned a[4];
            a[0] = uQ[(wrow + gid) * 36 + kk + tig];
            a[1] = uQ[(wrow + gid + 8) * 36 + kk + tig];
            a[2] = uQ[(wrow + gid) * 36 + kk + tig + 4];
            a[3] = uQ[(wrow + gid + 8) * 36 + kk + tig + 4];
#pragma unroll
            for (int nt = 0; nt < 8; ++nt) {
                unsigned bfr[2];
                bfr[0] = uK[(nt * 8 + gid) * 36 + kk + tig];
                bfr[1] = uK[(nt * 8 + gid) * 36 + kk + tig + 4];
                MMA_F16(s[nt], a, bfr);
            }
        }

        // ---- scale + mask + online softmax ----
        float mx0 = -1e30f, mx1 = -1e30f;
#pragma unroll
        for (int nt = 0; nt < 8; ++nt) {
            float q0 = msk[nt * 8 + 2 * tig], q1 = msk[nt * 8 + 2 * tig + 1];
            s[nt][0] = fmaf(s[nt][0], 0.125f, q0);
            s[nt][1] = fmaf(s[nt][1], 0.125f, q1);
            s[nt][2] = fmaf(s[nt][2], 0.125f, q0);
            s[nt][3] = fmaf(s[nt][3], 0.125f, q1);
            mx0 = fmaxf(mx0, fmaxf(s[nt][0], s[nt][1]));
            mx1 = fmaxf(mx1, fmaxf(s[nt][2], s[nt][3]));
        }
        mx0 = fmaxf(mx0, __shfl_xor_sync(0xffffffffu, mx0, 1));
        mx0 = fmaxf(mx0, __shfl_xor_sync(0xffffffffu, mx0, 2));
        mx1 = fmaxf(mx1, __shfl_xor_sync(0xffffffffu, mx1, 1));
        mx1 = fmaxf(mx1, __shfl_xor_sync(0xffffffffu, mx1, 2));

        float mn0 = fmaxf(m0, mx0), mn1 = fmaxf(m1, mx1);
        float la0 = 0.f, la1 = 0.f;
        unsigned* p0row = &uP[(wrow + gid) * 36];
        unsigned* p1row = &uP[(wrow + gid + 8) * 36];
#pragma unroll
        for (int nt = 0; nt < 8; ++nt) {
            float p0 = __expf(s[nt][0] - mn0);
            float p1 = __expf(s[nt][1] - mn0);
            float p2 = __expf(s[nt][2] - mn1);
            float p3 = __expf(s[nt][3] - mn1);
            la0 += p0 + p1; la1 += p2 + p3;
            p0row[nt * 4 + tig] = pack2h(p0, p1);
            p1row[nt * 4 + tig] = pack2h(p2, p3);
        }
        la0 += __shfl_xor_sync(0xffffffffu, la0, 1);
        la0 += __shfl_xor_sync(0xffffffffu, la0, 2);
        la1 += __shfl_xor_sync(0xffffffffu, la1, 1);
        la1 += __shfl_xor_sync(0xffffffffu, la1, 2);

        float al0 = __expf(m0 - mn0), al1 = __expf(m1 - mn1);
        l0 = l0 * al0 + la0;
        l1 = l1 * al1 + la1;
        m0 = mn0; m1 = mn1;
#pragma unroll
        for (int nt = 0; nt < 8; ++nt) {
            o[nt][0] *= al0; o[nt][1] *= al0;
            o[nt][2] *= al1; o[nt][3] *= al1;
        }
        __syncwarp();

        // ---- O += P @ V (4 k-steps over jp) ----
#pragma unroll
        for (int kb = 0; kb < 4; ++kb) {
            const int kk = kb * 8;
            unsigned a[4];
            a[0] = uP[(wrow + gid) * 36 + kk + tig];
            a[1] = uP[(wrow + gid + 8) * 36 + kk + tig];
            a[2] = uP[(wrow + gid) * 36 + kk + tig + 4];
            a[3] = uP[(wrow + gid + 8) * 36 + kk + tig + 4];
#pragma unroll
            for (int nt = 0; nt < 8; ++nt) {
                unsigned bfr[2];
                bfr[0] = uV[(kk + tig) * 68 + nt * 8 + gid];
                bfr[1] = uV[(kk + tig + 4) * 68 + nt * 8 + gid];
                MMA_F16(o[nt], a, bfr);
            }
        }
    }

    // ---- epilogue: normalize, pack, write concat words ----
    float inv0 = 1.f / l0, inv1 = 1.f / l1;
    int r0 = i0 + wrow + gid;
#pragma unroll
    for (int nt = 0; nt < 8; ++nt) {
        int wc = h * 32 + nt * 4 + tig;
        g_concat[(size_t)(r0 * BATCH + b) * 512 + wc]       = pack2h(o[nt][0] * inv0, o[nt][1] * inv0);
        g_concat[(size_t)((r0 + 8) * BATCH + b) * 512 + wc] = pack2h(o[nt][2] * inv1, o[nt][3] * inv1);
    }
}

// ---------------- entry point ----------------
extern "C" void kernel_launch(void* const* d_in, const int* in_sizes, int n_in,
                              void* d_out, int out_size) {
    const float* query    = (const float*)d_in[0];
    const float* key      = (const float*)d_in[1];
    const float* value    = (const float*)d_in[2];
    const int*   key_mask = (const int*)  d_in[3];
    const float* Wq = (const float*)d_in[4];
    const float* bq = (const float*)d_in[5];
    const float* Wk = (const float*)d_in[6];
    const float* bk = (const float*)d_in[7];
    const float* Wv = (const float*)d_in[8];
    const float* bv = (const float*)d_in[9];
    const float* Wo = (const float*)d_in[10];
    const float* bo = (const float*)d_in[11];
    float* out = (float*)d_out;

    cudaFuncSetAttribute(attn_kernel, cudaFuncAttributeMaxDynamicSharedMemorySize,
                         ATTN_SMEM_BYTES);

    prep_kernel<<<(NWRD + 255) / 256, 256>>>(query, key, value, Wq, Wk, Wv, bq, bk, bv, Wo);
    gemm_qkv_kernel<<<dim3(3 * DMODEL / 128, S_LEN * BATCH / 128), 256>>>();
    attn_kernel<<<dim3(S_LEN / 128, NHEAD, BATCH), 256, ATTN_SMEM_BYTES>>>(key_mask);
    gemm_out_kernel<<<dim3(DMODEL / 128, S_LEN * BATCH / 128), 256>>>(bo, out);
}

// round 10
// speedup vs baseline: 3.1355x; 1.0026x over previous
#include <cuda_runtime.h>
#include <cuda_fp16.h>
#include <math.h>

#define S_LEN  1024
#define BATCH  4
#define DMODEL 1024
#define NHEAD  16
#define DHEAD  64
#define NIN    (S_LEN * BATCH * DMODEL)
#define NWRD   (NIN / 2)                 // packed half2 words per input tensor

// ---------------- device scratch (packed half2 words) ----------------
__device__ unsigned g_in[3 * NWRD];                 // q/k/v packed along dmodel
__device__ unsigned g_Wt[512 * 3 * DMODEL];         // qkv weights [kp][which*1024+h*64+kk]
__device__ unsigned g_Wo[512 * DMODEL];             // Wo [kp][n]
__device__ float    g_bias[3 * DMODEL];
// head-major qkv words: (((which*4+b)*16+h)*1024 + s)*32 + dp
__device__ unsigned g_qkv[3 * BATCH * NHEAD * S_LEN * 32];
__device__ unsigned g_concat[S_LEN * BATCH * 512];  // [s*B+b][h*32+dp]

// ---------------- helpers ----------------
__device__ __forceinline__ unsigned pack2h(float a, float b) {
    __half2 h = __floats2half2_rn(a, b);
    return *(unsigned*)&h;
}

#define MMA_F16(d, a, b)                                                         \
    asm volatile(                                                                \
        "mma.sync.aligned.m16n8k16.row.col.f32.f16.f16.f32 "                     \
        "{%0,%1,%2,%3}, {%4,%5,%6,%7}, {%8,%9}, {%0,%1,%2,%3};"                  \
        : "+f"((d)[0]), "+f"((d)[1]), "+f"((d)[2]), "+f"((d)[3])                 \
        : "r"((a)[0]), "r"((a)[1]), "r"((a)[2]), "r"((a)[3]),                    \
          "r"((b)[0]), "r"((b)[1]))

// One ldmatrix.x4: loads a full 16x16 fp16 A-fragment (4 regs) from shared.
#define LDSM_X4(r, saddr)                                                        \
    asm volatile(                                                                \
        "ldmatrix.sync.aligned.m8n8.x4.shared.b16 {%0,%1,%2,%3}, [%4];"          \
        : "=r"((r)[0]), "=r"((r)[1]), "=r"((r)[2]), "=r"((r)[3])                 \
        : "r"(saddr))

// ---------------- prep: convert + pack everything to half2 words ----------------
__global__ void prep_kernel(const float* __restrict__ q, const float* __restrict__ k,
                            const float* __restrict__ v,
                            const float* __restrict__ Wq, const float* __restrict__ Wk,
                            const float* __restrict__ Wv,
                            const float* __restrict__ bq, const float* __restrict__ bk,
                            const float* __restrict__ bv, const float* __restrict__ Wo) {
    int t = blockIdx.x * blockDim.x + threadIdx.x;
    if (t < NWRD) {
        g_in[t]            = pack2h(q[2 * t], q[2 * t + 1]);
        g_in[NWRD + t]     = pack2h(k[2 * t], k[2 * t + 1]);
        g_in[2 * NWRD + t] = pack2h(v[2 * t], v[2 * t + 1]);
    }
    const int NWT = 512 * 3 * DMODEL;       // 1.5M
    if (t < NWT) {
        int kp = t / 3072, n = t - kp * 3072;
        int which = n >> 10, r = n & 1023;
        int h = r >> 6, kk = r & 63;
        const float* W = (which == 0) ? Wq : (which == 1) ? Wk : Wv;
        int base = (h * 1024 + 2 * kp) * 64 + kk;
        g_Wt[t] = pack2h(W[base], W[base + 64]);
    }
    const int NWO = 512 * DMODEL;
    if (t < NWO) {
        int kp = t >> 10, n = t & 1023;
        g_Wo[t] = pack2h(Wo[2 * kp * 1024 + n], Wo[(2 * kp + 1) * 1024 + n]);
    }
    if (t < 3 * DMODEL) {
        const float* bb = (t < 1024) ? bq : (t < 2048) ? bk : bv;
        g_bias[t] = bb[t & 1023];
    }
}

// ---------------- FP16 GEMM: 128x128x64 tile (32 words k), 8 warps ----------------
template<int REMAP>
__device__ __forceinline__ void gemm_body(
    const unsigned* __restrict__ A, int lda,       // words, row-major [m][kp]
    const unsigned* __restrict__ B, int ldb,       // words, [kp][n]
    const float* __restrict__ bias, void* __restrict__ Cout,
    int ldc, int m0, int n0)
{
    __shared__ unsigned As[128 * 36];   // [m][kp] pad 4
    __shared__ unsigned Bs[32 * 132];   // [kp][n] pad 4

    const int tid  = threadIdx.x;
    const int lane = tid & 31;
    const int wid  = tid >> 5;
    const int gid  = lane >> 2;
    const int tig  = lane & 3;
    const int wm   = (wid >> 2) * 64;
    const int wn   = (wid & 3) * 32;

    // per-lane ldmatrix base: row = wm + (lane&15), k-half select from lane bit4
    const unsigned asBase = (unsigned)__cvta_generic_to_shared(As);
    const unsigned aRow   = asBase + ((wm + (lane & 15)) * 36 + ((lane & 16) >> 2)) * 4;

    float acc[4][4][4];
#pragma unroll
    for (int mt = 0; mt < 4; ++mt)
#pragma unroll
        for (int nt = 0; nt < 4; ++nt)
#pragma unroll
            for (int r = 0; r < 4; ++r) acc[mt][nt][r] = 0.f;

    const int arow = tid >> 2;           // 0..63 (and +64)
    const int acol = (tid & 3) << 3;     // 0,8,16,24 (and +4)
    const int brow = tid >> 5;           // 0..7 (and +8,+16,+24)
    const int bcol = (tid & 31) << 2;    // 0..124

    const unsigned* Ap = A + (size_t)(m0 + arow) * lda + acol;
    const unsigned* Bp = B + (size_t)brow * ldb + n0 + bcol;

    uint4 ag[4], bg[4];
#pragma unroll
    for (int r = 0; r < 2; ++r) {
        ag[2 * r]     = *(const uint4*)(Ap + (size_t)(64 * r) * lda);
        ag[2 * r + 1] = *(const uint4*)(Ap + (size_t)(64 * r) * lda + 4);
    }
#pragma unroll
    for (int r = 0; r < 4; ++r)
        bg[r] = *(const uint4*)(Bp + (size_t)(8 * r) * ldb);

    for (int k0 = 0; k0 < 512; k0 += 32) {   // 16 k-tiles of 32 words (64 halves)
        __syncthreads();
#pragma unroll
        for (int r = 0; r < 2; ++r) {
            *(uint4*)&As[(arow + 64 * r) * 36 + acol]     = ag[2 * r];
            *(uint4*)&As[(arow + 64 * r) * 36 + acol + 4] = ag[2 * r + 1];
        }
#pragma unroll
        for (int r = 0; r < 4; ++r)
            *(uint4*)&Bs[(brow + 8 * r) * 132 + bcol] = bg[r];
        __syncthreads();

        if (k0 + 32 < 512) {
#pragma unroll
            for (int r = 0; r < 2; ++r) {
                ag[2 * r]     = *(const uint4*)(Ap + (size_t)(64 * r) * lda + k0 + 32);
                ag[2 * r + 1] = *(const uint4*)(Ap + (size_t)(64 * r) * lda + k0 + 36);
            }
#pragma unroll
            for (int r = 0; r < 4; ++r)
                bg[r] = *(const uint4*)(Bp + (size_t)(k0 + 32 + 8 * r) * ldb);
        }

#pragma unroll
        for (int kb = 0; kb < 4; ++kb) {
            const int kk = kb * 8;
            unsigned af[4][4], bf[4][2];
#pragma unroll
            for (int mt = 0; mt < 4; ++mt)
                LDSM_X4(af[mt], aRow + (mt * 16 * 36 + kk) * 4);
#pragma unroll
            for (int nt = 0; nt < 4; ++nt) {
                int c = wn + nt * 8 + gid;
                bf[nt][0] = Bs[(kk + tig) * 132 + c];
                bf[nt][1] = Bs[(kk + tig + 4) * 132 + c];
            }
#pragma unroll
            for (int mt = 0; mt < 4; ++mt)
#pragma unroll
                for (int nt = 0; nt < 4; ++nt)
                    MMA_F16(acc[mt][nt], af[mt], bf[nt]);
        }
    }

    // ---- epilogue ----
#pragma unroll
    for (int mt = 0; mt < 4; ++mt) {
        int row0 = m0 + wm + mt * 16 + gid;
#pragma unroll
        for (int nt = 0; nt < 4; ++nt) {
            int col = n0 + wn + nt * 8 + 2 * tig;
            float b0 = bias[col], b1 = bias[col + 1];
            float x0 = acc[mt][nt][0] + b0, y0 = acc[mt][nt][1] + b1;
            float x1 = acc[mt][nt][2] + b0, y1 = acc[mt][nt][3] + b1;
            if (!REMAP) {
                float* C = (float*)Cout;
                *(float2*)&C[(size_t)row0 * ldc + col]       = make_float2(x0, y0);
                *(float2*)&C[(size_t)(row0 + 8) * ldc + col] = make_float2(x1, y1);
            } else {
                unsigned* C = (unsigned*)Cout;
                int which = col >> 10, hh = (col >> 6) & 15, dp = (col & 63) >> 1;
                int s0 = row0 >> 2, b0i = row0 & 3;
                int s1 = (row0 + 8) >> 2, b1i = (row0 + 8) & 3;
                C[((((size_t)(which * 4 + b0i) * 16 + hh) * 1024 + s0) * 32) + dp] = pack2h(x0, y0);
                C[((((size_t)(which * 4 + b1i) * 16 + hh) * 1024 + s1) * 32) + dp] = pack2h(x1, y1);
            }
        }
    }
}

__global__ void __launch_bounds__(256, 2) gemm_qkv_kernel() {
    int n0 = blockIdx.x * 128;
    int m0 = blockIdx.y * 128;
    const unsigned* A = g_in + (size_t)(n0 >> 10) * NWRD;
    gemm_body<1>(A, 512, g_Wt, 3 * DMODEL, g_bias, g_qkv, 0, m0, n0);
}

__global__ void __launch_bounds__(256, 2) gemm_out_kernel(
    const float* __restrict__ bo, float* __restrict__ out) {
    int n0 = blockIdx.x * 128;
    int m0 = blockIdx.y * 128;
    gemm_body<0>(g_concat, 512, g_Wo, DMODEL, bo, out, DMODEL, m0, n0);
}

// ---------------- FP16 MMA flash attention ----------------
// smem words: uQ[128][36], uK[64][36], uV[32][68], uP[128][36], msk[64]
#define ATTN_SMEM_BYTES ((128 * 36 + 64 * 36 + 32 * 68 + 128 * 36 + 64) * 4)

__global__ void __launch_bounds__(256, 2) attn_kernel(const int* __restrict__ key_mask) {
    extern __shared__ unsigned sm[];
    unsigned* uQ = sm;                        // [128][36] A-operand, packed d
    unsigned* uK = uQ + 128 * 36;             // [64][36]  B-operand [n=j][kp=dp]
    unsigned* uV = uK + 64 * 36;              // [32][68]  B-operand [kp=jp][n=d]
    unsigned* uP = uV + 32 * 68;              // [128][36] A-operand, packed j
    float* msk   = (float*)(uP + 128 * 36);   // [64]

    const int b = blockIdx.z, h = blockIdx.y, i0 = blockIdx.x * 128;
    const int tid = threadIdx.x, lane = tid & 31, wid = tid >> 5;
    const int gid = lane >> 2, tig = lane & 3;
    const int wrow = wid * 16;

    // per-lane ldmatrix bases for the warp's 16-row A tiles in uQ / uP
    const unsigned lrow = (wrow + (lane & 15)) * 36 + ((lane & 16) >> 2);
    const unsigned qRow = (unsigned)__cvta_generic_to_shared(uQ) + lrow * 4;
    const unsigned pRow = (unsigned)__cvta_generic_to_shared(uP) + lrow * 4;

    const unsigned* Qg = g_qkv + (((size_t)(0 * 4 + b) * 16 + h) * 1024 + i0) * 32;
    const unsigned* Kg = g_qkv + (((size_t)(1 * 4 + b) * 16 + h) * 1024) * 32;
    const unsigned* Vg = g_qkv + (((size_t)(2 * 4 + b) * 16 + h) * 1024) * 32;

    // ---- stage Q (128 x 32 words) ----
    {
        const uint4* src = (const uint4*)Qg;
#pragma unroll
        for (int r = 0; r < 4; ++r) {
            int idx = tid + 256 * r;
            int i = idx >> 3, c4 = (idx & 7) << 2;
            *(uint4*)&uQ[i * 36 + c4] = src[idx];
        }
    }

    float m0 = -1e30f, m1 = -1e30f, l0 = 0.f, l1 = 0.f;
    float o[8][4];
#pragma unroll
    for (int nt = 0; nt < 8; ++nt)
#pragma unroll
        for (int r = 0; r < 4; ++r) o[nt][r] = 0.f;

    for (int jt = 0; jt < S_LEN / 64; ++jt) {
        const int j0 = jt * 64;
        __syncthreads();
        {
            // K: 64 x 32 words, natural layout
            const uint4* ks = (const uint4*)(Kg + (size_t)j0 * 32);
#pragma unroll
            for (int r = 0; r < 2; ++r) {
                int idx = tid + 256 * r;
                int j = idx >> 3, c4 = (idx & 7) << 2;
                *(uint4*)&uK[j * 36 + c4] = ks[idx];
            }
            // V: pack along j  (word(jp,d) = (V[2jp][d], V[2jp+1][d]))
            const uint4* vs = (const uint4*)(Vg + (size_t)j0 * 32);
            int jp = tid >> 3, c = tid & 7;
            uint4 r0 = vs[(2 * jp) * 8 + c];
            uint4 r1 = vs[(2 * jp + 1) * 8 + c];
            uint4 o0, o1;
            o0.x = __byte_perm(r0.x, r1.x, 0x5410); o0.y = __byte_perm(r0.x, r1.x, 0x7632);
            o0.z = __byte_perm(r0.y, r1.y, 0x5410); o0.w = __byte_perm(r0.y, r1.y, 0x7632);
            o1.x = __byte_perm(r0.z, r1.z, 0x5410); o1.y = __byte_perm(r0.z, r1.z, 0x7632);
            o1.z = __byte_perm(r0.w, r1.w, 0x5410); o1.w = __byte_perm(r0.w, r1.w, 0x7632);
            *(uint4*)&uV[jp * 68 + c * 8]     = o0;
            *(uint4*)&uV[jp * 68 + c * 8 + 4] = o1;

            if (tid < 64)
                msk[tid] = key_mask[(j0 + tid) * BATCH + b] ? -1e18f : 0.f;
        }
        __syncthreads();

        // ---- S = Q @ K^T (16x64 per warp, 4 k-steps) ----
        float s[8][4];
#pragma unroll
        for (int nt = 0; nt < 8; ++nt)
#pragma unroll
            for (int r = 0; r < 4; ++r) s[nt][r] = 0.f;
#pragma unroll
        for (int kb = 0; kb < 4; ++kb) {
            const int kk = kb * 8;
            unsigned a[4];
            LDSM_X4(a, qRow + kk * 4);
#pragma unroll
            for (int nt = 0; nt < 8; ++nt) {
                unsigned bfr[2];
                bfr[0] = uK[(nt * 8 + gid) * 36 + kk + tig];
                bfr[1] = uK[(nt * 8 + gid) * 36 + kk + tig + 4];
                MMA_F16(s[nt], a, bfr);
            }
        }

        // ---- scale + mask + online softmax ----
        float mx0 = -1e30f, mx1 = -1e30f;
#pragma unroll
        for (int nt = 0; nt < 8; ++nt) {
            float q0 = msk[nt * 8 + 2 * tig], q1 = msk[nt * 8 + 2 * tig + 1];
            s[nt][0] = fmaf(s[nt][0], 0.125f, q0);
            s[nt][1] = fmaf(s[nt][1], 0.125f, q1);
            s[nt][2] = fmaf(s[nt][2], 0.125f, q0);
            s[nt][3] = fmaf(s[nt][3], 0.125f, q1);
            mx0 = fmaxf(mx0, fmaxf(s[nt][0], s[nt][1]));
            mx1 = fmaxf(mx1, fmaxf(s[nt][2], s[nt][3]));
        }
        mx0 = fmaxf(mx0, __shfl_xor_sync(0xffffffffu, mx0, 1));
        mx0 = fmaxf(mx0, __shfl_xor_sync(0xffffffffu, mx0, 2));
        mx1 = fmaxf(mx1, __shfl_xor_sync(0xffffffffu, mx1, 1));
        mx1 = fmaxf(mx1, __shfl_xor_sync(0xffffffffu, mx1, 2));

        float mn0 = fmaxf(m0, mx0), mn1 = fmaxf(m1, mx1);
        float la0 = 0.f, la1 = 0.f;
        unsigned* p0row = &uP[(wrow + gid) * 36];
        unsigned* p1row = &uP[(wrow + gid + 8) * 36];
#pragma unroll
        for (int nt = 0; nt < 8; ++nt) {
            float p0 = __expf(s[nt][0] - mn0);
            float p1 = __expf(s[nt][1] - mn0);
            float p2 = __expf(s[nt][2] - mn1);
            float p3 = __expf(s[nt][3] - mn1);
            la0 += p0 + p1; la1 += p2 + p3;
            p0row[nt * 4 + tig] = pack2h(p0, p1);
            p1row[nt * 4 + tig] = pack2h(p2, p3);
        }
        la0 += __shfl_xor_sync(0xffffffffu, la0, 1);
        la0 += __shfl_xor_sync(0xffffffffu, la0, 2);
        la1 += __shfl_xor_sync(0xffffffffu, la1, 1);
        la1 += __shfl_xor_sync(0xffffffffu, la1, 2);

        float al0 = __expf(m0 - mn0), al1 = __expf(m1 - mn1);
        l0 = l0 * al0 + la0;
        l1 = l1 * al1 + la1;
        m0 = mn0; m1 = mn1;
#pragma unroll
        for (int nt = 0; nt < 8; ++nt) {
            o[nt][0] *= al0; o[nt][1] *= al0;
            o[nt][2] *= al1; o[nt][3] *= al1;
        }
        __syncwarp();

        // ---- O += P @ V (4 k-steps over jp) ----
#pragma unroll
        for (int kb = 0; kb < 4; ++kb) {
            const int kk = kb * 8;
            unsigned a[4];
            LDSM_X4(a, pRow + kk * 4);
#pragma unroll
            for (int nt = 0; nt < 8; ++nt) {
                unsigned bfr[2];
                bfr[0] = uV[(kk + tig) * 68 + nt * 8 + gid];
                bfr[1] = uV[(kk + tig + 4) * 68 + nt * 8 + gid];
                MMA_F16(o[nt], a, bfr);
            }
        }
    }

    // ---- epilogue: normalize, pack, write concat words ----
    float inv0 = 1.f / l0, inv1 = 1.f / l1;
    int r0 = i0 + wrow + gid;
#pragma unroll
    for (int nt = 0; nt < 8; ++nt) {
        int wc = h * 32 + nt * 4 + tig;
        g_concat[(size_t)(r0 * BATCH + b) * 512 + wc]       = pack2h(o[nt][0] * inv0, o[nt][1] * inv0);
        g_concat[(size_t)((r0 + 8) * BATCH + b) * 512 + wc] = pack2h(o[nt][2] * inv1, o[nt][3] * inv1);
    }
}

// ---------------- entry point ----------------
extern "C" void kernel_launch(void* const* d_in, const int* in_sizes, int n_in,
                              void* d_out, int out_size) {
    const float* query    = (const float*)d_in[0];
    const float* key      = (const float*)d_in[1];
    const float* value    = (const float*)d_in[2];
    const int*   key_mask = (const int*)  d_in[3];
    const float* Wq = (const float*)d_in[4];
    const float* bq = (const float*)d_in[5];
    const float* Wk = (const float*)d_in[6];
    const float* bk = (const float*)d_in[7];
    const float* Wv = (const float*)d_in[8];
    const float* bv = (const float*)d_in[9];
    const float* Wo = (const float*)d_in[10];
    const float* bo = (const float*)d_in[11];
    float* out = (float*)d_out;

    cudaFuncSetAttribute(attn_kernel, cudaFuncAttributeMaxDynamicSharedMemorySize,
                         ATTN_SMEM_BYTES);

    prep_kernel<<<(NWRD + 255) / 256, 256>>>(query, key, value, Wq, Wk, Wv, bq, bk, bv, Wo);
    gemm_qkv_kernel<<<dim3(3 * DMODEL / 128, S_LEN * BATCH / 128), 256>>>();
    attn_kernel<<<dim3(S_LEN / 128, NHEAD, BATCH), 256, ATTN_SMEM_BYTES>>>(key_mask);
    gemm_out_kernel<<<dim3(DMODEL / 128, S_LEN * BATCH / 128), 256>>>(bo, out);
}